// round 2
// baseline (speedup 1.0000x reference)
#include <cuda_runtime.h>
#include <math.h>

// ---------------------------------------------------------------------------
// TnoFFT: per-(b,d) channel long convolution via real-packed radix-8 FFT.
//   o[b,i,d] = sum_{j=0..4095} x[b,j,d] * t[(i-j) mod 8192, d],  i in [0,4096)
// Implemented as rfft(8192) -> pointwise -> irfft(8192) with the length-4096
// complex FFT done in shared memory, 4 d-channels per CTA.
// ---------------------------------------------------------------------------

#define NTHREADS 512
#define CPAD     4608            // padded per-channel stride (float2): 4096 + 4096/8
#define DATOFF   4608            // twiddle table occupies [0, 4608)
#define TSTRIDE  2052            // float4 slots per channel in g_T (2049 used)
#define SMEM_BYTES (CPAD * 5 * (int)sizeof(float2))   // 184320
#define PADA(j)  ((j) + ((j) >> 3))

static __device__ float4 g_T[1024 * TSTRIDE];   // precomputed rfft(t) pairs, ~33.6 MB

__device__ __forceinline__ float2 cadd(float2 a, float2 b){ return make_float2(a.x+b.x, a.y+b.y); }
__device__ __forceinline__ float2 csub(float2 a, float2 b){ return make_float2(a.x-b.x, a.y-b.y); }
__device__ __forceinline__ float2 cmul(float2 a, float2 b){
    return make_float2(a.x*b.x - a.y*b.y, a.x*b.y + a.y*b.x);
}
__device__ __forceinline__ float2 cmulj(float2 a, float2 b){ // a * conj(b)
    return make_float2(a.x*b.x + a.y*b.y, a.y*b.x - a.x*b.y);
}
__device__ __forceinline__ float2 mul_mi(float2 a){ return make_float2( a.y, -a.x); } // * -i
__device__ __forceinline__ float2 mul_pi(float2 a){ return make_float2(-a.y,  a.x); } // * +i

// 8-point DFT in registers. INV=false: e^{-2pi i/8}; INV=true: conjugate, unscaled.
template<bool INV>
__device__ __forceinline__ void dft8(float2 u[8]){
    const float C0 = 0.70710678118654752440f;
    float2 e0,e1,e2,e3,o0,o1,o2,o3;
    {
        float2 s0=cadd(u[0],u[4]), d0=csub(u[0],u[4]);
        float2 s1=cadd(u[2],u[6]), d1=csub(u[2],u[6]);
        e0=cadd(s0,s1); e2=csub(s0,s1);
        float2 jd = INV ? mul_pi(d1) : mul_mi(d1);
        e1=cadd(d0,jd); e3=csub(d0,jd);
    }
    {
        float2 s0=cadd(u[1],u[5]), d0=csub(u[1],u[5]);
        float2 s1=cadd(u[3],u[7]), d1=csub(u[3],u[7]);
        o0=cadd(s0,s1); o2=csub(s0,s1);
        float2 jd = INV ? mul_pi(d1) : mul_mi(d1);
        o1=cadd(d0,jd); o3=csub(d0,jd);
    }
    float2 t0 = o0, t1, t2, t3;
    if (!INV) {
        t1 = make_float2(C0*(o1.x + o1.y), C0*(o1.y - o1.x));   // * C(1-i)
        t2 = mul_mi(o2);                                        // * -i
        t3 = make_float2(C0*(o3.y - o3.x), -C0*(o3.x + o3.y));  // * C(-1-i)
    } else {
        t1 = make_float2(C0*(o1.x - o1.y), C0*(o1.y + o1.x));   // * C(1+i)
        t2 = mul_pi(o2);                                        // * +i
        t3 = make_float2(-C0*(o3.x + o3.y), C0*(o3.x - o3.y));  // * C(-1+i)
    }
    u[0]=cadd(e0,t0); u[4]=csub(e0,t0);
    u[1]=cadd(e1,t1); u[5]=csub(e1,t1);
    u[2]=cadd(e2,t2); u[6]=csub(e2,t2);
    u[3]=cadd(e3,t3); u[7]=csub(e3,t3);
}

// 12-bit radix-8 digit reversal (involution).
__device__ __forceinline__ int rev12(int k){
    return ((k & 7) << 9) | (((k >> 3) & 7) << 6) | (((k >> 6) & 7) << 3) | ((k >> 9) & 7);
}
// Permuted pair-loop index -> natural frequency k (bijection [0,2048) -> [0,2048)).
// Lane-varying bits land in k's middle digit so scrambled-order smem accesses
// spread across banks while g_T stays contiguous in m.
__device__ __forceinline__ int kOfM(int m){
    int d2 = m & 7;
    int h  = m >> 3;
    int d1 = h & 7;
    int d0 = (h >> 3) & 7;
    int d3 = (h >> 6);           // 0..3
    return (d3 << 9) | (d2 << 6) | (d1 << 3) | d0;
}

// In-place length-4096 FFT over one channel (128 threads per channel, 4 ch/CTA).
// Forward (INV=false): radix-8 DIF, natural in -> digit-reversed out, unscaled.
// Inverse (INV=true):  radix-8 DIT, digit-reversed in -> natural out, scaled by 4096
//                      (caller folds 1/4096 into the data beforehand).
// Caller must __syncthreads() before the first call; each stage syncs after itself.
template<bool INV>
__device__ __forceinline__ void fft_stages(float2* __restrict__ ch,
                                           const float2* __restrict__ tw, int lane){
    #pragma unroll
    for (int st = 0; st < 4; ++st) {
        const int s     = INV ? (1 << (3*st)) : (512 >> (3*st));
        const int mstep = 4096 / (8 * s);
        #pragma unroll
        for (int i = 0; i < 4; ++i) {
            int t    = lane + (i << 7);
            int jp   = t & (s - 1);
            int base = ((t - jp) << 3) + jp;
            float2 u[8];
            #pragma unroll
            for (int q = 0; q < 8; ++q) u[q] = ch[PADA(base + q*s)];
            if (INV) {
                if (s > 1) {
                    float2 w1 = tw[PADA(jp * mstep)];
                    w1.y = -w1.y;
                    float2 w2 = cmul(w1,w1), w3 = cmul(w1,w2), w4 = cmul(w2,w2);
                    float2 w5 = cmul(w2,w3), w6 = cmul(w3,w3), w7 = cmul(w3,w4);
                    u[1]=cmul(u[1],w1); u[2]=cmul(u[2],w2); u[3]=cmul(u[3],w3);
                    u[4]=cmul(u[4],w4); u[5]=cmul(u[5],w5); u[6]=cmul(u[6],w6);
                    u[7]=cmul(u[7],w7);
                }
                dft8<true>(u);
            } else {
                dft8<false>(u);
                if (s > 1) {
                    float2 w1 = tw[PADA(jp * mstep)];
                    float2 w2 = cmul(w1,w1), w3 = cmul(w1,w2), w4 = cmul(w2,w2);
                    float2 w5 = cmul(w2,w3), w6 = cmul(w3,w3), w7 = cmul(w3,w4);
                    u[1]=cmul(u[1],w1); u[2]=cmul(u[2],w2); u[3]=cmul(u[3],w3);
                    u[4]=cmul(u[4],w4); u[5]=cmul(u[5],w5); u[6]=cmul(u[6],w6);
                    u[7]=cmul(u[7],w7);
                }
            }
            #pragma unroll
            for (int q = 0; q < 8; ++q) ch[PADA(base + q*s)] = u[q];
        }
        __syncthreads();
    }
}

__device__ __forceinline__ void build_twiddles(float2* tw, int tid){
    const float w = -2.0f * 3.14159265358979323846f / 4096.0f;
    #pragma unroll
    for (int i = 0; i < 8; ++i) {
        int idx = tid + NTHREADS * i;
        float sv, cv;
        sincosf(w * (float)idx, &sv, &cv);
        tw[PADA(idx)] = make_float2(cv, sv);
    }
}

// ---------------------------------------------------------------------------
// Kernel A: T[k] = rfft(t, 8192) per d-channel, stored as (T[k], T[4096-k])
// float4 pairs at permuted index m (plus slot 2048 for the self-paired bin).
// ---------------------------------------------------------------------------
__global__ void __launch_bounds__(NTHREADS, 1)
tfft_kernel(const float* __restrict__ t)
{
    extern __shared__ float2 sm[];
    float2* tw = sm;
    const int tid  = threadIdx.x;
    const int ch   = tid >> 7;
    const int lane = tid & 127;
    float2* chd = sm + DATOFF + ch * CPAD;

    build_twiddles(tw, tid);
    float w0s, w0c;
    sincosf(-3.14159265358979323846f / 4096.0f, &w0s, &w0c);
    const float2 W0 = make_float2(w0c, w0s);

    const int dtile = blockIdx.x;                       // 0..255
    const float4* t4 = (const float4*)t + dtile;

    // stage in: z[j] = t[2j] + i t[2j+1], j = 0..4095
    #pragma unroll
    for (int i = 0; i < 8; ++i) {
        int j = tid + NTHREADS * i;
        float4 ve = t4[(size_t)(2*j)   * 256];
        float4 vo = t4[(size_t)(2*j+1) * 256];
        int a = PADA(j);
        sm[DATOFF + 0*CPAD + a] = make_float2(ve.x, vo.x);
        sm[DATOFF + 1*CPAD + a] = make_float2(ve.y, vo.y);
        sm[DATOFF + 2*CPAD + a] = make_float2(ve.z, vo.z);
        sm[DATOFF + 3*CPAD + a] = make_float2(ve.w, vo.w);
    }
    __syncthreads();

    fft_stages<false>(chd, tw, lane);

    float4* Tch = g_T + (size_t)(dtile*4 + ch) * TSTRIDE;
    for (int i = 0; i < 16; ++i) {
        int m = lane + (i << 7);
        if (m == 0) {
            float2 Z0 = chd[PADA(0)];
            Tch[0] = make_float4(Z0.x + Z0.y, 0.f, Z0.x - Z0.y, 0.f);   // (T[0], T[4096])
        } else {
            int k  = kOfM(m);
            float2 Zk = chd[PADA(rev12(k))];
            float2 Zm = chd[PADA(rev12(4096 - k))];
            float2 A = make_float2(0.5f*(Zk.x + Zm.x), 0.5f*(Zk.y - Zm.y));
            float2 B = make_float2(0.5f*(Zk.x - Zm.x), 0.5f*(Zk.y + Zm.y));
            float2 w = tw[PADA(k >> 1)];
            if (k & 1) w = cmul(w, W0);                 // e^{-i pi k / 4096}
            float2 WB = cmul(w, B);
            float2 Xk = make_float2(A.x + WB.y,  A.y - WB.x);
            float2 Xm = make_float2(A.x - WB.y, -(A.y + WB.x));
            Tch[m] = make_float4(Xk.x, Xk.y, Xm.x, Xm.y);
        }
    }
    if (lane == 0) {                                    // k = 2048 (self-paired), pos rev=4
        float2 Z = chd[PADA(4)];
        Tch[2048] = make_float4(Z.x, -Z.y, 0.f, 0.f);
    }
}

// ---------------------------------------------------------------------------
// Kernel B: per (b, d-tile): rfft(x pad 8192) -> * T -> irfft -> first 4096.
// ---------------------------------------------------------------------------
__global__ void __launch_bounds__(NTHREADS, 1)
conv_kernel(const float* __restrict__ x, float* __restrict__ out)
{
    extern __shared__ float2 sm[];
    float2* tw = sm;
    const int tid  = threadIdx.x;
    const int ch   = tid >> 7;
    const int lane = tid & 127;
    float2* chd = sm + DATOFF + ch * CPAD;

    build_twiddles(tw, tid);
    float w0s, w0c;
    sincosf(-3.14159265358979323846f / 4096.0f, &w0s, &w0c);
    const float2 W0 = make_float2(w0c, w0s);

    const int blk   = blockIdx.x;                       // 0..1023
    const int b     = blk >> 8;
    const int dtile = blk & 255;
    const float4* x4 = (const float4*)x + (size_t)b * 4096 * 256 + dtile;

    // stage in: z[j] = x[2j] + i x[2j+1] for j<2048; zero-pad j in [2048,4096)
    #pragma unroll
    for (int i = 0; i < 4; ++i) {
        int j = tid + NTHREADS * i;                     // 0..2047
        float4 ve = x4[(size_t)(2*j)   * 256];
        float4 vo = x4[(size_t)(2*j+1) * 256];
        int a = PADA(j);
        sm[DATOFF + 0*CPAD + a] = make_float2(ve.x, vo.x);
        sm[DATOFF + 1*CPAD + a] = make_float2(ve.y, vo.y);
        sm[DATOFF + 2*CPAD + a] = make_float2(ve.z, vo.z);
        sm[DATOFF + 3*CPAD + a] = make_float2(ve.w, vo.w);
    }
    #pragma unroll
    for (int i = 0; i < 4; ++i) {
        int j = 2048 + tid + NTHREADS * i;
        int a = PADA(j);
        float2 z = make_float2(0.f, 0.f);
        sm[DATOFF + 0*CPAD + a] = z;
        sm[DATOFF + 1*CPAD + a] = z;
        sm[DATOFF + 2*CPAD + a] = z;
        sm[DATOFF + 3*CPAD + a] = z;
    }
    __syncthreads();

    fft_stages<false>(chd, tw, lane);

    // unpack -> multiply by T -> repack, all in scrambled order; fold 1/4096.
    const float4* Tch = g_T + (size_t)(dtile*4 + ch) * TSTRIDE;
    const float invM = 1.0f / 4096.0f;
    for (int i = 0; i < 16; ++i) {
        int m = lane + (i << 7);
        float4 Tp = Tch[m];
        if (m == 0) {
            float2 Z0 = chd[PADA(0)];
            float X0 = Z0.x + Z0.y;                     // X[0]
            float XM = Z0.x - Z0.y;                     // X[4096]
            float Y0 = X0 * Tp.x;
            float YM = XM * Tp.z;
            chd[PADA(0)] = make_float2(0.5f*(Y0+YM)*invM, 0.5f*(Y0-YM)*invM);
        } else {
            int k  = kOfM(m);
            int p1 = PADA(rev12(k));
            int p2 = PADA(rev12(4096 - k));
            float2 Zk = chd[p1];
            float2 Zm = chd[p2];
            float2 A = make_float2(0.5f*(Zk.x + Zm.x), 0.5f*(Zk.y - Zm.y));
            float2 B = make_float2(0.5f*(Zk.x - Zm.x), 0.5f*(Zk.y + Zm.y));
            float2 w = tw[PADA(k >> 1)];
            if (k & 1) w = cmul(w, W0);                 // e^{-i pi k / 4096}
            float2 WB = cmul(w, B);
            float2 Xk = make_float2(A.x + WB.y,  A.y - WB.x);
            float2 Xm = make_float2(A.x - WB.y, -(A.y + WB.x));
            float2 Yk = cmul(Xk, make_float2(Tp.x, Tp.y));
            float2 Ym = cmul(Xm, make_float2(Tp.z, Tp.w));
            float2 Cc = make_float2(0.5f*(Yk.x + Ym.x), 0.5f*(Yk.y - Ym.y));
            float2 Dd = make_float2(0.5f*(Yk.x - Ym.x), 0.5f*(Yk.y + Ym.y));
            float2 VD = cmulj(Dd, w);                   // conj(w) * D
            chd[p1] = make_float2((Cc.x - VD.y)*invM, ( Cc.y + VD.x)*invM);
            chd[p2] = make_float2((Cc.x + VD.y)*invM, (-Cc.y + VD.x)*invM);
        }
    }
    if (lane == 0) {                                    // k = 2048, pos rev=4
        float4 Tp = Tch[2048];
        float2 Z  = chd[PADA(4)];
        float2 X  = make_float2(Z.x, -Z.y);             // X[2048] = conj(Z[2048])
        float2 Y  = cmul(X, make_float2(Tp.x, Tp.y));
        chd[PADA(4)] = make_float2(Y.x * invM, -Y.y * invM);
    }
    __syncthreads();

    fft_stages<true>(chd, tw, lane);

    // stage out: y[2j] = Re z[j], y[2j+1] = Im z[j], j = 0..2047 (first 4096 samples)
    float4* o4 = (float4*)out + (size_t)b * 4096 * 256 + dtile;
    #pragma unroll
    for (int i = 0; i < 4; ++i) {
        int j = tid + NTHREADS * i;                     // 0..2047
        int a = PADA(j);
        float2 z0 = sm[DATOFF + 0*CPAD + a];
        float2 z1 = sm[DATOFF + 1*CPAD + a];
        float2 z2 = sm[DATOFF + 2*CPAD + a];
        float2 z3 = sm[DATOFF + 3*CPAD + a];
        o4[(size_t)(2*j)   * 256] = make_float4(z0.x, z1.x, z2.x, z3.x);
        o4[(size_t)(2*j+1) * 256] = make_float4(z0.y, z1.y, z2.y, z3.y);
    }
}

extern "C" void kernel_launch(void* const* d_in, const int* in_sizes, int n_in,
                              void* d_out, int out_size)
{
    const float* x = (const float*)d_in[0];   // (4, 4096, 1024) f32
    const float* t = (const float*)d_in[1];   // (8192, 1024) f32
    float* out = (float*)d_out;               // (4, 4096, 1024) f32

    cudaFuncSetAttribute(tfft_kernel, cudaFuncAttributeMaxDynamicSharedMemorySize, SMEM_BYTES);
    cudaFuncSetAttribute(conv_kernel, cudaFuncAttributeMaxDynamicSharedMemorySize, SMEM_BYTES);

    tfft_kernel<<<256, NTHREADS, SMEM_BYTES>>>(t);
    conv_kernel<<<1024, NTHREADS, SMEM_BYTES>>>(x, out);
}

// round 4
// speedup vs baseline: 1.0055x; 1.0055x over previous
#include <cuda_runtime.h>
#include <math.h>

// ---------------------------------------------------------------------------
// TnoFFT: per-(b,d) channel long convolution via real-packed radix-8 FFT.
//   o[b,i,d] = sum_{j=0..4095} x[b,j,d] * t[(i-j) mod 8192, d],  i in [0,4096)
// rfft(8192) -> pointwise -> irfft(8192); length-4096 complex FFT in shared
// memory, 4 independent d-channels per CTA with per-channel named barriers.
// ---------------------------------------------------------------------------

#define NTHREADS 512
#define CPAD     4608            // padded per-channel stride (float2)
#define TWPAD    2304            // padded twiddle slots (covers PADA(2047)=2302)
#define DATOFF   TWPAD           // channel data starts after twiddle table
#define TSTRIDE  2052            // float4 slots per channel in g_T (2049 used)
#define SMEM_BYTES ((TWPAD + 4 * CPAD) * (int)sizeof(float2))   // 165888
#define PADA(j)  ((j) + ((j) >> 3))

// W0 = e^{-i*pi/4096}
#define W0_RE 0.9999997058549675f
#define W0_IM (-7.6699031874270453e-4f)

static __device__ float4 g_T[1024 * TSTRIDE];   // precomputed rfft(t) pairs, ~33.6 MB
static __device__ float2 g_twp[TWPAD];          // padded twiddle image (zero-init gaps)

__device__ __forceinline__ float2 cadd(float2 a, float2 b){ return make_float2(a.x+b.x, a.y+b.y); }
__device__ __forceinline__ float2 csub(float2 a, float2 b){ return make_float2(a.x-b.x, a.y-b.y); }
__device__ __forceinline__ float2 cmul(float2 a, float2 b){
    return make_float2(a.x*b.x - a.y*b.y, a.x*b.y + a.y*b.x);
}
__device__ __forceinline__ float2 cmulj(float2 a, float2 b){ // a * conj(b)
    return make_float2(a.x*b.x + a.y*b.y, a.y*b.x - a.x*b.y);
}
__device__ __forceinline__ float2 mul_mi(float2 a){ return make_float2( a.y, -a.x); } // * -i
__device__ __forceinline__ float2 mul_pi(float2 a){ return make_float2(-a.y,  a.x); } // * +i

__device__ __forceinline__ void chan_sync(int bar_id){
    asm volatile("bar.sync %0, 128;" :: "r"(bar_id) : "memory");
}

// 8-point DFT in registers. INV=false: e^{-2pi i/8}; INV=true: conjugate, unscaled.
template<bool INV>
__device__ __forceinline__ void dft8(float2 u[8]){
    const float C0 = 0.70710678118654752440f;
    float2 e0,e1,e2,e3,o0,o1,o2,o3;
    {
        float2 s0=cadd(u[0],u[4]), d0=csub(u[0],u[4]);
        float2 s1=cadd(u[2],u[6]), d1=csub(u[2],u[6]);
        e0=cadd(s0,s1); e2=csub(s0,s1);
        float2 jd = INV ? mul_pi(d1) : mul_mi(d1);
        e1=cadd(d0,jd); e3=csub(d0,jd);
    }
    {
        float2 s0=cadd(u[1],u[5]), d0=csub(u[1],u[5]);
        float2 s1=cadd(u[3],u[7]), d1=csub(u[3],u[7]);
        o0=cadd(s0,s1); o2=csub(s0,s1);
        float2 jd = INV ? mul_pi(d1) : mul_mi(d1);
        o1=cadd(d0,jd); o3=csub(d0,jd);
    }
    float2 t0 = o0, t1, t2, t3;
    if (!INV) {
        t1 = make_float2(C0*(o1.x + o1.y), C0*(o1.y - o1.x));   // * C(1-i)
        t2 = mul_mi(o2);                                        // * -i
        t3 = make_float2(C0*(o3.y - o3.x), -C0*(o3.x + o3.y));  // * C(-1-i)
    } else {
        t1 = make_float2(C0*(o1.x - o1.y), C0*(o1.y + o1.x));   // * C(1+i)
        t2 = mul_pi(o2);                                        // * +i
        t3 = make_float2(-C0*(o3.x + o3.y), C0*(o3.x - o3.y));  // * C(-1+i)
    }
    u[0]=cadd(e0,t0); u[4]=csub(e0,t0);
    u[1]=cadd(e1,t1); u[5]=csub(e1,t1);
    u[2]=cadd(e2,t2); u[6]=csub(e2,t2);
    u[3]=cadd(e3,t3); u[7]=csub(e3,t3);
}

// 12-bit radix-8 digit reversal (involution).
__device__ __forceinline__ int rev12(int k){
    return ((k & 7) << 9) | (((k >> 3) & 7) << 6) | (((k >> 6) & 7) << 3) | ((k >> 9) & 7);
}
// Permuted pair-loop index -> natural frequency k (bijection [0,2048) -> [0,2048)).
__device__ __forceinline__ int kOfM(int m){
    int d2 = m & 7;
    int h  = m >> 3;
    int d1 = h & 7;
    int d0 = (h >> 3) & 7;
    int d3 = (h >> 6);           // 0..3
    return (d3 << 9) | (d2 << 6) | (d1 << 3) | d0;
}

// In-place length-4096 FFT over one channel (128 threads per channel).
// Forward: radix-8 DIF, natural -> digit-reversed. Inverse: DIT, reversed -> natural.
// Per-channel named barrier after each stage (channels stay independent).
template<bool INV>
__device__ __forceinline__ void fft_stages(float2* __restrict__ ch,
                                           const float2* __restrict__ tw,
                                           int lane, int bar_id){
    #pragma unroll
    for (int st = 0; st < 4; ++st) {
        const int s     = INV ? (1 << (3*st)) : (512 >> (3*st));
        const int mstep = 4096 / (8 * s);
        #pragma unroll
        for (int i = 0; i < 4; ++i) {
            int t    = lane + (i << 7);
            int jp   = t & (s - 1);
            int base = ((t - jp) << 3) + jp;
            float2 u[8];
            #pragma unroll
            for (int q = 0; q < 8; ++q) u[q] = ch[PADA(base + q*s)];
            if (INV) {
                if (s > 1) {
                    float2 w1 = tw[PADA(jp * mstep)];
                    w1.y = -w1.y;
                    float2 w2 = cmul(w1,w1), w3 = cmul(w1,w2), w4 = cmul(w2,w2);
                    float2 w5 = cmul(w2,w3), w6 = cmul(w3,w3), w7 = cmul(w3,w4);
                    u[1]=cmul(u[1],w1); u[2]=cmul(u[2],w2); u[3]=cmul(u[3],w3);
                    u[4]=cmul(u[4],w4); u[5]=cmul(u[5],w5); u[6]=cmul(u[6],w6);
                    u[7]=cmul(u[7],w7);
                }
                dft8<true>(u);
            } else {
                dft8<false>(u);
                if (s > 1) {
                    float2 w1 = tw[PADA(jp * mstep)];
                    float2 w2 = cmul(w1,w1), w3 = cmul(w1,w2), w4 = cmul(w2,w2);
                    float2 w5 = cmul(w2,w3), w6 = cmul(w3,w3), w7 = cmul(w3,w4);
                    u[1]=cmul(u[1],w1); u[2]=cmul(u[2],w2); u[3]=cmul(u[3],w3);
                    u[4]=cmul(u[4],w4); u[5]=cmul(u[5],w5); u[6]=cmul(u[6],w6);
                    u[7]=cmul(u[7],w7);
                }
            }
            #pragma unroll
            for (int q = 0; q < 8; ++q) ch[PADA(base + q*s)] = u[q];
        }
        chan_sync(bar_id);
    }
}

// Copy padded twiddle image from gmem into smem (float4 vectors).
__device__ __forceinline__ void copy_twiddles(float2* tw, int tid){
    const float4* src = (const float4*)g_twp;
    float4* dst = (float4*)tw;
    #pragma unroll
    for (int i = 0; i < 3; ++i) {
        int idx = tid + NTHREADS * i;
        if (idx < TWPAD / 2) dst[idx] = src[idx];
    }
}

// ---------------------------------------------------------------------------
// Kernel 0: build padded twiddle table in gmem (once per launch; tiny).
// ---------------------------------------------------------------------------
__global__ void twinit_kernel()
{
    int j = blockIdx.x * blockDim.x + threadIdx.x;     // 0..2047
    if (j < 2048) {
        const float w = -2.0f * 3.14159265358979323846f / 4096.0f;
        float sv, cv;
        sincosf(w * (float)j, &sv, &cv);
        g_twp[PADA(j)] = make_float2(cv, sv);
    }
}

// ---------------------------------------------------------------------------
// Kernel A: T[k] = rfft(t, 8192) per d-channel, stored as (T[k], T[4096-k])
// float4 pairs at permuted index m (plus slot 2048 for the self-paired bin).
// ---------------------------------------------------------------------------
__global__ void __launch_bounds__(NTHREADS, 1)
tfft_kernel(const float* __restrict__ t)
{
    extern __shared__ float2 sm[];
    float2* tw = sm;
    const int tid  = threadIdx.x;
    const int ch   = tid >> 7;
    const int lane = tid & 127;
    const int bar  = ch + 1;
    float2* chd = sm + DATOFF + ch * CPAD;

    copy_twiddles(tw, tid);
    const float2 W0 = make_float2(W0_RE, W0_IM);

    const int dtile = blockIdx.x;                       // 0..255
    const float4* t4 = (const float4*)t + dtile;

    // stage in: z[j] = t[2j] + i t[2j+1], j = 0..4095
    #pragma unroll
    for (int i = 0; i < 8; ++i) {
        int j = tid + NTHREADS * i;
        float4 ve = t4[(size_t)(2*j)   * 256];
        float4 vo = t4[(size_t)(2*j+1) * 256];
        int a = PADA(j);
        sm[DATOFF + 0*CPAD + a] = make_float2(ve.x, vo.x);
        sm[DATOFF + 1*CPAD + a] = make_float2(ve.y, vo.y);
        sm[DATOFF + 2*CPAD + a] = make_float2(ve.z, vo.z);
        sm[DATOFF + 3*CPAD + a] = make_float2(ve.w, vo.w);
    }
    __syncthreads();                                    // cross-channel staging

    fft_stages<false>(chd, tw, lane, bar);

    float4* Tch = g_T + (size_t)(dtile*4 + ch) * TSTRIDE;
    for (int i = 0; i < 16; ++i) {
        int m = lane + (i << 7);
        if (m == 0) {
            float2 Z0 = chd[PADA(0)];
            Tch[0] = make_float4(Z0.x + Z0.y, 0.f, Z0.x - Z0.y, 0.f);   // (T[0], T[4096])
        } else {
            int k  = kOfM(m);
            float2 Zk = chd[PADA(rev12(k))];
            float2 Zm = chd[PADA(rev12(4096 - k))];
            float2 A = make_float2(0.5f*(Zk.x + Zm.x), 0.5f*(Zk.y - Zm.y));
            float2 B = make_float2(0.5f*(Zk.x - Zm.x), 0.5f*(Zk.y + Zm.y));
            float2 w = tw[PADA(k >> 1)];
            if (k & 1) w = cmul(w, W0);                 // e^{-i pi k / 4096}
            float2 WB = cmul(w, B);
            float2 Xk = make_float2(A.x + WB.y,  A.y - WB.x);
            float2 Xm = make_float2(A.x - WB.y, -(A.y + WB.x));
            Tch[m] = make_float4(Xk.x, Xk.y, Xm.x, Xm.y);
        }
    }
    if (lane == 0) {                                    // k = 2048 (self-paired), pos rev=4
        float2 Z = chd[PADA(4)];
        Tch[2048] = make_float4(Z.x, -Z.y, 0.f, 0.f);
    }
}

// ---------------------------------------------------------------------------
// Kernel B: per (b, d-tile): rfft(x pad 8192) -> * T -> irfft -> first 4096.
// ---------------------------------------------------------------------------
__global__ void __launch_bounds__(NTHREADS, 1)
conv_kernel(const float* __restrict__ x, float* __restrict__ out)
{
    extern __shared__ float2 sm[];
    float2* tw = sm;
    const int tid  = threadIdx.x;
    const int ch   = tid >> 7;
    const int lane = tid & 127;
    const int bar  = ch + 1;
    float2* chd = sm + DATOFF + ch * CPAD;

    copy_twiddles(tw, tid);
    const float2 W0 = make_float2(W0_RE, W0_IM);

    const int blk   = blockIdx.x;                       // 0..1023
    const int b     = blk >> 8;
    const int dtile = blk & 255;
    const float4* x4 = (const float4*)x + (size_t)b * 4096 * 256 + dtile;

    // stage in: z[j] = x[2j] + i x[2j+1] for j<2048; zero-pad j in [2048,4096)
    #pragma unroll
    for (int i = 0; i < 4; ++i) {
        int j = tid + NTHREADS * i;                     // 0..2047
        float4 ve = x4[(size_t)(2*j)   * 256];
        float4 vo = x4[(size_t)(2*j+1) * 256];
        int a = PADA(j);
        sm[DATOFF + 0*CPAD + a] = make_float2(ve.x, vo.x);
        sm[DATOFF + 1*CPAD + a] = make_float2(ve.y, vo.y);
        sm[DATOFF + 2*CPAD + a] = make_float2(ve.z, vo.z);
        sm[DATOFF + 3*CPAD + a] = make_float2(ve.w, vo.w);
    }
    #pragma unroll
    for (int i = 0; i < 4; ++i) {
        int j = 2048 + tid + NTHREADS * i;
        int a = PADA(j);
        float2 z = make_float2(0.f, 0.f);
        sm[DATOFF + 0*CPAD + a] = z;
        sm[DATOFF + 1*CPAD + a] = z;
        sm[DATOFF + 2*CPAD + a] = z;
        sm[DATOFF + 3*CPAD + a] = z;
    }
    __syncthreads();                                    // cross-channel staging

    fft_stages<false>(chd, tw, lane, bar);

    // unpack -> multiply by T -> repack, all in scrambled order; fold 1/4096.
    const float4* Tch = g_T + (size_t)(dtile*4 + ch) * TSTRIDE;
    const float invM = 1.0f / 4096.0f;
    for (int i = 0; i < 16; ++i) {
        int m = lane + (i << 7);
        float4 Tp = Tch[m];
        if (m == 0) {
            float2 Z0 = chd[PADA(0)];
            float X0 = Z0.x + Z0.y;                     // X[0]
            float XM = Z0.x - Z0.y;                     // X[4096]
            float Y0 = X0 * Tp.x;
            float YM = XM * Tp.z;
            chd[PADA(0)] = make_float2(0.5f*(Y0+YM)*invM, 0.5f*(Y0-YM)*invM);
        } else {
            int k  = kOfM(m);
            int p1 = PADA(rev12(k));
            int p2 = PADA(rev12(4096 - k));
            float2 Zk = chd[p1];
            float2 Zm = chd[p2];
            float2 A = make_float2(0.5f*(Zk.x + Zm.x), 0.5f*(Zk.y - Zm.y));
            float2 B = make_float2(0.5f*(Zk.x - Zm.x), 0.5f*(Zk.y + Zm.y));
            float2 w = tw[PADA(k >> 1)];
            if (k & 1) w = cmul(w, W0);                 // e^{-i pi k / 4096}
            float2 WB = cmul(w, B);
            float2 Xk = make_float2(A.x + WB.y,  A.y - WB.x);
            float2 Xm = make_float2(A.x - WB.y, -(A.y + WB.x));
            float2 Yk = cmul(Xk, make_float2(Tp.x, Tp.y));
            float2 Ym = cmul(Xm, make_float2(Tp.z, Tp.w));
            float2 Cc = make_float2(0.5f*(Yk.x + Ym.x), 0.5f*(Yk.y - Ym.y));
            float2 Dd = make_float2(0.5f*(Yk.x - Ym.x), 0.5f*(Yk.y + Ym.y));
            float2 VD = cmulj(Dd, w);                   // conj(w) * D
            chd[p1] = make_float2((Cc.x - VD.y)*invM, ( Cc.y + VD.x)*invM);
            chd[p2] = make_float2((Cc.x + VD.y)*invM, (-Cc.y + VD.x)*invM);
        }
    }
    if (lane == 0) {                                    // k = 2048, pos rev=4
        float4 Tp = Tch[2048];
        float2 Z  = chd[PADA(4)];
        float2 X  = make_float2(Z.x, -Z.y);             // X[2048] = conj(Z[2048])
        float2 Y  = cmul(X, make_float2(Tp.x, Tp.y));
        chd[PADA(4)] = make_float2(Y.x * invM, -Y.y * invM);
    }
    chan_sync(bar);                                     // per-channel: pointwise done

    fft_stages<true>(chd, tw, lane, bar);

    __syncthreads();                                    // cross-channel before stage-out

    // stage out: y[2j] = Re z[j], y[2j+1] = Im z[j], j = 0..2047 (first 4096 samples)
    float4* o4 = (float4*)out + (size_t)b * 4096 * 256 + dtile;
    #pragma unroll
    for (int i = 0; i < 4; ++i) {
        int j = tid + NTHREADS * i;                     // 0..2047
        int a = PADA(j);
        float2 z0 = sm[DATOFF + 0*CPAD + a];
        float2 z1 = sm[DATOFF + 1*CPAD + a];
        float2 z2 = sm[DATOFF + 2*CPAD + a];
        float2 z3 = sm[DATOFF + 3*CPAD + a];
        o4[(size_t)(2*j)   * 256] = make_float4(z0.x, z1.x, z2.x, z3.x);
        o4[(size_t)(2*j+1) * 256] = make_float4(z0.y, z1.y, z2.y, z3.y);
    }
}

extern "C" void kernel_launch(void* const* d_in, const int* in_sizes, int n_in,
                              void* d_out, int out_size)
{
    const float* x = (const float*)d_in[0];   // (4, 4096, 1024) f32
    const float* t = (const float*)d_in[1];   // (8192, 1024) f32
    float* out = (float*)d_out;               // (4, 4096, 1024) f32

    cudaFuncSetAttribute(tfft_kernel, cudaFuncAttributeMaxDynamicSharedMemorySize, SMEM_BYTES);
    cudaFuncSetAttribute(conv_kernel, cudaFuncAttributeMaxDynamicSharedMemorySize, SMEM_BYTES);

    twinit_kernel<<<4, NTHREADS>>>();
    tfft_kernel<<<256, NTHREADS, SMEM_BYTES>>>(t);
    conv_kernel<<<1024, NTHREADS, SMEM_BYTES>>>(x, out);
}

// round 6
// speedup vs baseline: 1.0685x; 1.0627x over previous
#include <cuda_runtime.h>
#include <math.h>

// ---------------------------------------------------------------------------
// TnoFFT: per-(b,d) channel long convolution via real-packed radix-8 FFT.
//   o[b,i,d] = sum_{j=0..4095} x[b,j,d] * t[(i-j) mod 8192, d],  i in [0,4096)
// rfft(8192) -> pointwise -> irfft(8192); length-4096 complex FFT in shared
// memory, 4 independent d-channels per CTA. Butterfly add/subs use packed
// f32x2 (FFMA2/FADD2) to cut issue count.
// ---------------------------------------------------------------------------

#define NTHREADS 512
#define CPAD     4608            // padded per-channel stride (float2)
#define TWPAD    2304            // padded twiddle slots (covers PADA(2047)=2302)
#define DATOFF   TWPAD           // channel data starts after twiddle table
#define TSTRIDE  2052            // float4 slots per channel in g_T (2049 used)
#define SMEM_BYTES ((TWPAD + 4 * CPAD) * (int)sizeof(float2))   // 165888
#define PADA(j)  ((j) + ((j) >> 3))

// W0 = e^{-i*pi/4096}
#define W0_RE 0.9999997058549675f
#define W0_IM (-7.6699031874270453e-4f)

static __device__ float4 g_T[1024 * TSTRIDE];   // precomputed rfft(t) pairs, ~33.6 MB
static __device__ float2 g_twp[TWPAD];          // padded twiddle image (zero-init gaps)

// ---------------- packed f32x2 helpers (sm_103a FADD2/FFMA2) ----------------
__device__ __forceinline__ float2 padd(float2 a, float2 b){
    unsigned int rx, ry;
    asm("{\n\t"
        ".reg .b64 ra, rb, rc;\n\t"
        "mov.b64 ra, {%2, %3};\n\t"
        "mov.b64 rb, {%4, %5};\n\t"
        "add.rn.f32x2 rc, ra, rb;\n\t"
        "mov.b64 {%0, %1}, rc;\n\t"
        "}" : "=r"(rx), "=r"(ry)
            : "r"(__float_as_uint(a.x)), "r"(__float_as_uint(a.y)),
              "r"(__float_as_uint(b.x)), "r"(__float_as_uint(b.y)));
    return make_float2(__uint_as_float(rx), __uint_as_float(ry));
}
__device__ __forceinline__ float2 psub(float2 a, float2 b){    // a - b via FFMA2
    unsigned int rx, ry;
    asm("{\n\t"
        ".reg .b64 ra, rb, rc, rn;\n\t"
        "mov.b64 rn, 0xBF800000BF800000;\n\t"
        "mov.b64 ra, {%2, %3};\n\t"
        "mov.b64 rb, {%4, %5};\n\t"
        "fma.rn.f32x2 rc, rb, rn, ra;\n\t"
        "mov.b64 {%0, %1}, rc;\n\t"
        "}" : "=r"(rx), "=r"(ry)
            : "r"(__float_as_uint(a.x)), "r"(__float_as_uint(a.y)),
              "r"(__float_as_uint(b.x)), "r"(__float_as_uint(b.y)));
    return make_float2(__uint_as_float(rx), __uint_as_float(ry));
}

__device__ __forceinline__ float2 cadd(float2 a, float2 b){ return padd(a, b); }
__device__ __forceinline__ float2 csub(float2 a, float2 b){ return psub(a, b); }
__device__ __forceinline__ float2 cmul(float2 a, float2 b){
    return make_float2(a.x*b.x - a.y*b.y, a.x*b.y + a.y*b.x);
}
__device__ __forceinline__ float2 cmulj(float2 a, float2 b){ // a * conj(b)
    return make_float2(a.x*b.x + a.y*b.y, a.y*b.x - a.x*b.y);
}

__device__ __forceinline__ void chan_sync(int bar_id){
    asm volatile("bar.sync %0, 128;" :: "r"(bar_id) : "memory");
}

// 8-point DFT in registers. INV=false: e^{-2pi i/8}; INV=true: conjugate, unscaled.
// Lane-uniform add/subs are packed f32x2; cross-lane twists stay scalar.
template<bool INV>
__device__ __forceinline__ void dft8(float2 u[8]){
    const float C0 = 0.70710678118654752440f;
    float2 e0,e1,e2,e3,o0,o1,o2,o3;
    {
        float2 s0=padd(u[0],u[4]), d0=psub(u[0],u[4]);
        float2 s1=padd(u[2],u[6]), d1=psub(u[2],u[6]);
        e0=padd(s0,s1); e2=psub(s0,s1);
        float2 jd = INV ? make_float2(-d1.y, d1.x) : make_float2(d1.y, -d1.x);
        e1=padd(d0,jd); e3=psub(d0,jd);
    }
    {
        float2 s0=padd(u[1],u[5]), d0=psub(u[1],u[5]);
        float2 s1=padd(u[3],u[7]), d1=psub(u[3],u[7]);
        o0=padd(s0,s1); o2=psub(s0,s1);
        float2 jd = INV ? make_float2(-d1.y, d1.x) : make_float2(d1.y, -d1.x);
        o1=padd(d0,jd); o3=psub(d0,jd);
    }
    float2 t0 = o0, t1, t2, t3;
    if (!INV) {
        t1 = make_float2(C0*(o1.x + o1.y), C0*(o1.y - o1.x));   // * C(1-i)
        t2 = make_float2(o2.y, -o2.x);                          // * -i
        t3 = make_float2(C0*(o3.y - o3.x), -C0*(o3.x + o3.y));  // * C(-1-i)
    } else {
        t1 = make_float2(C0*(o1.x - o1.y), C0*(o1.y + o1.x));   // * C(1+i)
        t2 = make_float2(-o2.y, o2.x);                          // * +i
        t3 = make_float2(-C0*(o3.x + o3.y), C0*(o3.x - o3.y));  // * C(-1+i)
    }
    u[0]=padd(e0,t0); u[4]=psub(e0,t0);
    u[1]=padd(e1,t1); u[5]=psub(e1,t1);
    u[2]=padd(e2,t2); u[6]=psub(e2,t2);
    u[3]=padd(e3,t3); u[7]=psub(e3,t3);
}

// 12-bit radix-8 digit reversal (involution).
__device__ __forceinline__ int rev12(int k){
    return ((k & 7) << 9) | (((k >> 3) & 7) << 6) | (((k >> 6) & 7) << 3) | ((k >> 9) & 7);
}
// Permuted pair-loop index -> natural frequency k (bijection [0,2048) -> [0,2048)).
__device__ __forceinline__ int kOfM(int m){
    int d2 = m & 7;
    int h  = m >> 3;
    int d1 = h & 7;
    int d0 = (h >> 3) & 7;
    int d3 = (h >> 6);           // 0..3
    return (d3 << 9) | (d2 << 6) | (d1 << 3) | d0;
}

// In-place length-4096 FFT over one channel (128 threads per channel).
// Forward: radix-8 DIF, natural -> digit-reversed. Inverse: DIT, reversed -> natural.
// Per-channel named barrier after each stage (channels stay independent).
template<bool INV>
__device__ __forceinline__ void fft_stages(float2* __restrict__ ch,
                                           const float2* __restrict__ tw,
                                           int lane, int bar_id){
    #pragma unroll
    for (int st = 0; st < 4; ++st) {
        const int s     = INV ? (1 << (3*st)) : (512 >> (3*st));
        const int mstep = 4096 / (8 * s);
        #pragma unroll
        for (int i = 0; i < 4; ++i) {
            int t    = lane + (i << 7);
            int jp   = t & (s - 1);
            int base = ((t - jp) << 3) + jp;
            float2 u[8];
            #pragma unroll
            for (int q = 0; q < 8; ++q) u[q] = ch[PADA(base + q*s)];
            if (INV) {
                if (s > 1) {
                    float2 w1 = tw[PADA(jp * mstep)];
                    w1.y = -w1.y;
                    float2 w2 = cmul(w1,w1), w3 = cmul(w1,w2), w4 = cmul(w2,w2);
                    float2 w5 = cmul(w2,w3), w6 = cmul(w3,w3), w7 = cmul(w3,w4);
                    u[1]=cmul(u[1],w1); u[2]=cmul(u[2],w2); u[3]=cmul(u[3],w3);
                    u[4]=cmul(u[4],w4); u[5]=cmul(u[5],w5); u[6]=cmul(u[6],w6);
                    u[7]=cmul(u[7],w7);
                }
                dft8<true>(u);
            } else {
                dft8<false>(u);
                if (s > 1) {
                    float2 w1 = tw[PADA(jp * mstep)];
                    float2 w2 = cmul(w1,w1), w3 = cmul(w1,w2), w4 = cmul(w2,w2);
                    float2 w5 = cmul(w2,w3), w6 = cmul(w3,w3), w7 = cmul(w3,w4);
                    u[1]=cmul(u[1],w1); u[2]=cmul(u[2],w2); u[3]=cmul(u[3],w3);
                    u[4]=cmul(u[4],w4); u[5]=cmul(u[5],w5); u[6]=cmul(u[6],w6);
                    u[7]=cmul(u[7],w7);
                }
            }
            #pragma unroll
            for (int q = 0; q < 8; ++q) ch[PADA(base + q*s)] = u[q];
        }
        chan_sync(bar_id);
    }
}

// Copy padded twiddle image from gmem into smem (float4 vectors).
__device__ __forceinline__ void copy_twiddles(float2* tw, int tid){
    const float4* src = (const float4*)g_twp;
    float4* dst = (float4*)tw;
    #pragma unroll
    for (int i = 0; i < 3; ++i) {
        int idx = tid + NTHREADS * i;
        if (idx < TWPAD / 2) dst[idx] = src[idx];
    }
}

// ---------------------------------------------------------------------------
// Kernel 0: build padded twiddle table in gmem (once per launch; tiny).
// ---------------------------------------------------------------------------
__global__ void twinit_kernel()
{
    int j = blockIdx.x * blockDim.x + threadIdx.x;     // 0..2047
    if (j < 2048) {
        const float w = -2.0f * 3.14159265358979323846f / 4096.0f;
        float sv, cv;
        sincosf(w * (float)j, &sv, &cv);
        g_twp[PADA(j)] = make_float2(cv, sv);
    }
}

// ---------------------------------------------------------------------------
// Kernel A: T[k] = rfft(t, 8192) per d-channel, stored as (T[k], T[4096-k])
// float4 pairs at permuted index m (plus slot 2048 for the self-paired bin).
// ---------------------------------------------------------------------------
__global__ void __launch_bounds__(NTHREADS, 1)
tfft_kernel(const float* __restrict__ t)
{
    extern __shared__ float2 sm[];
    float2* tw = sm;
    const int tid  = threadIdx.x;
    const int ch   = tid >> 7;
    const int lane = tid & 127;
    const int bar  = ch + 1;
    float2* chd = sm + DATOFF + ch * CPAD;

    copy_twiddles(tw, tid);
    const float2 W0 = make_float2(W0_RE, W0_IM);

    const int dtile = blockIdx.x;                       // 0..255
    const float4* t4 = (const float4*)t + dtile;

    // stage in: z[j] = t[2j] + i t[2j+1], j = 0..4095
    #pragma unroll
    for (int i = 0; i < 8; ++i) {
        int j = tid + NTHREADS * i;
        float4 ve = t4[(size_t)(2*j)   * 256];
        float4 vo = t4[(size_t)(2*j+1) * 256];
        int a = PADA(j);
        sm[DATOFF + 0*CPAD + a] = make_float2(ve.x, vo.x);
        sm[DATOFF + 1*CPAD + a] = make_float2(ve.y, vo.y);
        sm[DATOFF + 2*CPAD + a] = make_float2(ve.z, vo.z);
        sm[DATOFF + 3*CPAD + a] = make_float2(ve.w, vo.w);
    }
    __syncthreads();                                    // cross-channel staging

    fft_stages<false>(chd, tw, lane, bar);

    float4* Tch = g_T + (size_t)(dtile*4 + ch) * TSTRIDE;
    for (int i = 0; i < 16; ++i) {
        int m = lane + (i << 7);
        if (m == 0) {
            float2 Z0 = chd[PADA(0)];
            Tch[0] = make_float4(Z0.x + Z0.y, 0.f, Z0.x - Z0.y, 0.f);   // (T[0], T[4096])
        } else {
            int k  = kOfM(m);
            float2 Zk = chd[PADA(rev12(k))];
            float2 Zm = chd[PADA(rev12(4096 - k))];
            float2 A = make_float2(0.5f*(Zk.x + Zm.x), 0.5f*(Zk.y - Zm.y));
            float2 B = make_float2(0.5f*(Zk.x - Zm.x), 0.5f*(Zk.y + Zm.y));
            float2 w = tw[PADA(k >> 1)];
            if (k & 1) w = cmul(w, W0);                 // e^{-i pi k / 4096}
            float2 WB = cmul(w, B);
            float2 Xk = make_float2(A.x + WB.y,  A.y - WB.x);
            float2 Xm = make_float2(A.x - WB.y, -(A.y + WB.x));
            Tch[m] = make_float4(Xk.x, Xk.y, Xm.x, Xm.y);
        }
    }
    if (lane == 0) {                                    // k = 2048 (self-paired), pos rev=4
        float2 Z = chd[PADA(4)];
        Tch[2048] = make_float4(Z.x, -Z.y, 0.f, 0.f);
    }
}

// ---------------------------------------------------------------------------
// Kernel B: per (b, d-tile): rfft(x pad 8192) -> * T -> irfft -> first 4096.
// ---------------------------------------------------------------------------
__global__ void __launch_bounds__(NTHREADS, 1)
conv_kernel(const float* __restrict__ x, float* __restrict__ out)
{
    extern __shared__ float2 sm[];
    float2* tw = sm;
    const int tid  = threadIdx.x;
    const int ch   = tid >> 7;
    const int lane = tid & 127;
    const int bar  = ch + 1;
    float2* chd = sm + DATOFF + ch * CPAD;

    copy_twiddles(tw, tid);
    const float2 W0 = make_float2(W0_RE, W0_IM);

    const int blk   = blockIdx.x;                       // 0..1023
    const int b     = blk >> 8;
    const int dtile = blk & 255;
    const float4* x4 = (const float4*)x + (size_t)b * 4096 * 256 + dtile;

    // stage in: z[j] = x[2j] + i x[2j+1] for j<2048; zero-pad j in [2048,4096)
    #pragma unroll
    for (int i = 0; i < 4; ++i) {
        int j = tid + NTHREADS * i;                     // 0..2047
        float4 ve = x4[(size_t)(2*j)   * 256];
        float4 vo = x4[(size_t)(2*j+1) * 256];
        int a = PADA(j);
        sm[DATOFF + 0*CPAD + a] = make_float2(ve.x, vo.x);
        sm[DATOFF + 1*CPAD + a] = make_float2(ve.y, vo.y);
        sm[DATOFF + 2*CPAD + a] = make_float2(ve.z, vo.z);
        sm[DATOFF + 3*CPAD + a] = make_float2(ve.w, vo.w);
    }
    #pragma unroll
    for (int i = 0; i < 4; ++i) {
        int j = 2048 + tid + NTHREADS * i;
        int a = PADA(j);
        float2 z = make_float2(0.f, 0.f);
        sm[DATOFF + 0*CPAD + a] = z;
        sm[DATOFF + 1*CPAD + a] = z;
        sm[DATOFF + 2*CPAD + a] = z;
        sm[DATOFF + 3*CPAD + a] = z;
    }
    __syncthreads();                                    // cross-channel staging

    fft_stages<false>(chd, tw, lane, bar);

    // unpack -> multiply by T -> repack, all in scrambled order; fold 1/4096.
    const float4* Tch = g_T + (size_t)(dtile*4 + ch) * TSTRIDE;
    const float invM = 1.0f / 4096.0f;
    for (int i = 0; i < 16; ++i) {
        int m = lane + (i << 7);
        float4 Tp = Tch[m];
        if (m == 0) {
            float2 Z0 = chd[PADA(0)];
            float X0 = Z0.x + Z0.y;                     // X[0]
            float XM = Z0.x - Z0.y;                     // X[4096]
            float Y0 = X0 * Tp.x;
            float YM = XM * Tp.z;
            chd[PADA(0)] = make_float2(0.5f*(Y0+YM)*invM, 0.5f*(Y0-YM)*invM);
        } else {
            int k  = kOfM(m);
            int p1 = PADA(rev12(k));
            int p2 = PADA(rev12(4096 - k));
            float2 Zk = chd[p1];
            float2 Zm = chd[p2];
            float2 A = make_float2(0.5f*(Zk.x + Zm.x), 0.5f*(Zk.y - Zm.y));
            float2 B = make_float2(0.5f*(Zk.x - Zm.x), 0.5f*(Zk.y + Zm.y));
            float2 w = tw[PADA(k >> 1)];
            if (k & 1) w = cmul(w, W0);                 // e^{-i pi k / 4096}
            float2 WB = cmul(w, B);
            float2 Xk = make_float2(A.x + WB.y,  A.y - WB.x);
            float2 Xm = make_float2(A.x - WB.y, -(A.y + WB.x));
            float2 Yk = cmul(Xk, make_float2(Tp.x, Tp.y));
            float2 Ym = cmul(Xm, make_float2(Tp.z, Tp.w));
            float2 Cc = make_float2(0.5f*(Yk.x + Ym.x), 0.5f*(Yk.y - Ym.y));
            float2 Dd = make_float2(0.5f*(Yk.x - Ym.x), 0.5f*(Yk.y + Ym.y));
            float2 VD = cmulj(Dd, w);                   // conj(w) * D
            chd[p1] = make_float2((Cc.x - VD.y)*invM, ( Cc.y + VD.x)*invM);
            chd[p2] = make_float2((Cc.x + VD.y)*invM, (-Cc.y + VD.x)*invM);
        }
    }
    if (lane == 0) {                                    // k = 2048, pos rev=4
        float4 Tp = Tch[2048];
        float2 Z  = chd[PADA(4)];
        float2 X  = make_float2(Z.x, -Z.y);             // X[2048] = conj(Z[2048])
        float2 Y  = cmul(X, make_float2(Tp.x, Tp.y));
        chd[PADA(4)] = make_float2(Y.x * invM, -Y.y * invM);
    }
    chan_sync(bar);                                     // per-channel: pointwise done

    fft_stages<true>(chd, tw, lane, bar);

    __syncthreads();                                    // cross-channel before stage-out

    // stage out: y[2j] = Re z[j], y[2j+1] = Im z[j], j = 0..2047 (first 4096 samples)
    float4* o4 = (float4*)out + (size_t)b * 4096 * 256 + dtile;
    #pragma unroll
    for (int i = 0; i < 4; ++i) {
        int j = tid + NTHREADS * i;                     // 0..2047
        int a = PADA(j);
        float2 z0 = sm[DATOFF + 0*CPAD + a];
        float2 z1 = sm[DATOFF + 1*CPAD + a];
        float2 z2 = sm[DATOFF + 2*CPAD + a];
        float2 z3 = sm[DATOFF + 3*CPAD + a];
        o4[(size_t)(2*j)   * 256] = make_float4(z0.x, z1.x, z2.x, z3.x);
        o4[(size_t)(2*j+1) * 256] = make_float4(z0.y, z1.y, z2.y, z3.y);
    }
}

extern "C" void kernel_launch(void* const* d_in, const int* in_sizes, int n_in,
                              void* d_out, int out_size)
{
    const float* x = (const float*)d_in[0];   // (4, 4096, 1024) f32
    const float* t = (const float*)d_in[1];   // (8192, 1024) f32
    float* out = (float*)d_out;               // (4, 4096, 1024) f32

    cudaFuncSetAttribute(tfft_kernel, cudaFuncAttributeMaxDynamicSharedMemorySize, SMEM_BYTES);
    cudaFuncSetAttribute(conv_kernel, cudaFuncAttributeMaxDynamicSharedMemorySize, SMEM_BYTES);

    twinit_kernel<<<4, NTHREADS>>>();
    tfft_kernel<<<256, NTHREADS, SMEM_BYTES>>>(t);
    conv_kernel<<<1024, NTHREADS, SMEM_BYTES>>>(x, out);
}

// round 7
// speedup vs baseline: 1.0694x; 1.0008x over previous
#include <cuda_runtime.h>
#include <math.h>

// ---------------------------------------------------------------------------
// TnoFFT: per-(b,d) channel long convolution via real-packed radix-8 FFT.
//   o[b,i,d] = sum_{j=0..4095} x[b,j,d] * t[(i-j) mod 8192, d],  i in [0,4096)
// rfft(8192) -> pointwise -> irfft(8192); length-4096 complex FFT in shared
// memory, 4 independent d-channels per CTA. Packed f32x2 butterflies,
// load-hoisted stages (MLP ~36), zero-pad input skip + half-output skip.
// ---------------------------------------------------------------------------

#define NTHREADS 512
#define CPAD     4608            // padded per-channel stride (float2)
#define TWPAD    2304            // padded twiddle slots (covers PADA(2047)=2302)
#define DATOFF   TWPAD           // channel data starts after twiddle table
#define TSTRIDE  2052            // float4 slots per channel in g_T (2049 used)
#define SMEM_BYTES ((TWPAD + 4 * CPAD) * (int)sizeof(float2))   // 165888
#define PADA(j)  ((j) + ((j) >> 3))

// W0 = e^{-i*pi/4096}
#define W0_RE 0.9999997058549675f
#define W0_IM (-7.6699031874270453e-4f)

static __device__ float4 g_T[1024 * TSTRIDE];   // precomputed rfft(t) pairs, ~33.6 MB
static __device__ float2 g_twp[TWPAD];          // padded twiddle image (zero-init gaps)

// ---------------- packed f32x2 helpers (sm_103a FADD2/FFMA2) ----------------
__device__ __forceinline__ float2 padd(float2 a, float2 b){
    unsigned int rx, ry;
    asm("{\n\t"
        ".reg .b64 ra, rb, rc;\n\t"
        "mov.b64 ra, {%2, %3};\n\t"
        "mov.b64 rb, {%4, %5};\n\t"
        "add.rn.f32x2 rc, ra, rb;\n\t"
        "mov.b64 {%0, %1}, rc;\n\t"
        "}" : "=r"(rx), "=r"(ry)
            : "r"(__float_as_uint(a.x)), "r"(__float_as_uint(a.y)),
              "r"(__float_as_uint(b.x)), "r"(__float_as_uint(b.y)));
    return make_float2(__uint_as_float(rx), __uint_as_float(ry));
}
__device__ __forceinline__ float2 psub(float2 a, float2 b){    // a - b via FFMA2
    unsigned int rx, ry;
    asm("{\n\t"
        ".reg .b64 ra, rb, rc, rn;\n\t"
        "mov.b64 rn, 0xBF800000BF800000;\n\t"
        "mov.b64 ra, {%2, %3};\n\t"
        "mov.b64 rb, {%4, %5};\n\t"
        "fma.rn.f32x2 rc, rb, rn, ra;\n\t"
        "mov.b64 {%0, %1}, rc;\n\t"
        "}" : "=r"(rx), "=r"(ry)
            : "r"(__float_as_uint(a.x)), "r"(__float_as_uint(a.y)),
              "r"(__float_as_uint(b.x)), "r"(__float_as_uint(b.y)));
    return make_float2(__uint_as_float(rx), __uint_as_float(ry));
}

__device__ __forceinline__ float2 cmul(float2 a, float2 b){
    return make_float2(a.x*b.x - a.y*b.y, a.x*b.y + a.y*b.x);
}
__device__ __forceinline__ float2 cmulj(float2 a, float2 b){ // a * conj(b)
    return make_float2(a.x*b.x + a.y*b.y, a.y*b.x - a.x*b.y);
}

__device__ __forceinline__ void chan_sync(int bar_id){
    asm volatile("bar.sync %0, 128;" :: "r"(bar_id) : "memory");
}

// 8-point DFT in registers. INV=false: e^{-2pi i/8}; INV=true: conjugate, unscaled.
template<bool INV>
__device__ __forceinline__ void dft8(float2 u[8]){
    const float C0 = 0.70710678118654752440f;
    float2 e0,e1,e2,e3,o0,o1,o2,o3;
    {
        float2 s0=padd(u[0],u[4]), d0=psub(u[0],u[4]);
        float2 s1=padd(u[2],u[6]), d1=psub(u[2],u[6]);
        e0=padd(s0,s1); e2=psub(s0,s1);
        float2 jd = INV ? make_float2(-d1.y, d1.x) : make_float2(d1.y, -d1.x);
        e1=padd(d0,jd); e3=psub(d0,jd);
    }
    {
        float2 s0=padd(u[1],u[5]), d0=psub(u[1],u[5]);
        float2 s1=padd(u[3],u[7]), d1=psub(u[3],u[7]);
        o0=padd(s0,s1); o2=psub(s0,s1);
        float2 jd = INV ? make_float2(-d1.y, d1.x) : make_float2(d1.y, -d1.x);
        o1=padd(d0,jd); o3=psub(d0,jd);
    }
    float2 t0 = o0, t1, t2, t3;
    if (!INV) {
        t1 = make_float2(C0*(o1.x + o1.y), C0*(o1.y - o1.x));   // * C(1-i)
        t2 = make_float2(o2.y, -o2.x);                          // * -i
        t3 = make_float2(C0*(o3.y - o3.x), -C0*(o3.x + o3.y));  // * C(-1-i)
    } else {
        t1 = make_float2(C0*(o1.x - o1.y), C0*(o1.y + o1.x));   // * C(1+i)
        t2 = make_float2(-o2.y, o2.x);                          // * +i
        t3 = make_float2(-C0*(o3.x + o3.y), C0*(o3.x - o3.y));  // * C(-1+i)
    }
    u[0]=padd(e0,t0); u[4]=psub(e0,t0);
    u[1]=padd(e1,t1); u[5]=psub(e1,t1);
    u[2]=padd(e2,t2); u[6]=psub(e2,t2);
    u[3]=padd(e3,t3); u[7]=psub(e3,t3);
}

// Forward-only 8-point DFT with u[4..7] == 0 implicit (zero-padded input).
__device__ __forceinline__ void dft8h(float2 u[8]){
    const float C0 = 0.70710678118654752440f;
    float2 e0=padd(u[0],u[2]), e2=psub(u[0],u[2]);
    float2 jd = make_float2(u[2].y, -u[2].x);       // -i * u2
    float2 e1=padd(u[0],jd), e3=psub(u[0],jd);
    float2 o0=padd(u[1],u[3]), o2=psub(u[1],u[3]);
    float2 jo = make_float2(u[3].y, -u[3].x);       // -i * u3
    float2 o1=padd(u[1],jo), o3=psub(u[1],jo);
    float2 t0 = o0;
    float2 t1 = make_float2(C0*(o1.x + o1.y), C0*(o1.y - o1.x));
    float2 t2 = make_float2(o2.y, -o2.x);
    float2 t3 = make_float2(C0*(o3.y - o3.x), -C0*(o3.x + o3.y));
    u[0]=padd(e0,t0); u[4]=psub(e0,t0);
    u[1]=padd(e1,t1); u[5]=psub(e1,t1);
    u[2]=padd(e2,t2); u[6]=psub(e2,t2);
    u[3]=padd(e3,t3); u[7]=psub(e3,t3);
}

// 12-bit radix-8 digit reversal (involution).
__device__ __forceinline__ int rev12(int k){
    return ((k & 7) << 9) | (((k >> 3) & 7) << 6) | (((k >> 6) & 7) << 3) | ((k >> 9) & 7);
}
// Permuted pair-loop index -> natural frequency k (bijection [0,2048) -> [0,2048)).
__device__ __forceinline__ int kOfM(int m){
    int d2 = m & 7;
    int h  = m >> 3;
    int d1 = h & 7;
    int d0 = (h >> 3) & 7;
    int d3 = (h >> 6);           // 0..3
    return (d3 << 9) | (d2 << 6) | (d1 << 3) | d0;
}

// In-place length-4096 FFT over one channel (128 threads per channel).
// Forward: radix-8 DIF, natural -> digit-reversed. Inverse: DIT, reversed -> natural.
// All 36 loads of a stage are hoisted ahead of the math (MLP), per-channel barrier.
// HALF_IN  (forward only): input points >= 2048 are implicit zeros (skip loads).
// HALF_OUT (inverse only): output points >= 2048 are never read (skip stores).
template<bool INV, bool HALF_IN, bool HALF_OUT>
__device__ __forceinline__ void fft_stages(float2* __restrict__ ch,
                                           const float2* __restrict__ tw,
                                           int lane, int bar_id){
    #pragma unroll
    for (int st = 0; st < 4; ++st) {
        const int s     = INV ? (1 << (3*st)) : (512 >> (3*st));
        const int mstep = 4096 / (8 * s);
        const bool half_in  = (!INV) && HALF_IN  && (st == 0);   // s==512, base==t
        const bool half_out = INV    && HALF_OUT && (st == 3);   // s==512, base==t
        float2 u[4][8];
        float2 w1v[4];
        int    baseA[4];
        // ---- load phase: hoist every LDS of this stage ----
        #pragma unroll
        for (int i = 0; i < 4; ++i) {
            int t    = lane + (i << 7);
            int jp   = t & (s - 1);
            int base = ((t - jp) << 3) + jp;
            baseA[i] = base;
            if (s > 1) w1v[i] = tw[PADA(jp * mstep)];
            #pragma unroll
            for (int q = 0; q < 8; ++q) {
                if (half_in && q >= 4) continue;        // implicit zero
                u[i][q] = ch[PADA(base + q*s)];
            }
        }
        // ---- compute + store phase ----
        #pragma unroll
        for (int i = 0; i < 4; ++i) {
            if (INV) {
                if (s > 1) {
                    float2 w1 = w1v[i];
                    w1.y = -w1.y;
                    float2 w2 = cmul(w1,w1), w3 = cmul(w1,w2), w4 = cmul(w2,w2);
                    float2 w5 = cmul(w2,w3), w6 = cmul(w3,w3), w7 = cmul(w3,w4);
                    u[i][1]=cmul(u[i][1],w1); u[i][2]=cmul(u[i][2],w2); u[i][3]=cmul(u[i][3],w3);
                    u[i][4]=cmul(u[i][4],w4); u[i][5]=cmul(u[i][5],w5); u[i][6]=cmul(u[i][6],w6);
                    u[i][7]=cmul(u[i][7],w7);
                }
                dft8<true>(u[i]);
            } else {
                if (half_in) dft8h(u[i]);
                else         dft8<false>(u[i]);
                if (s > 1) {
                    float2 w1 = w1v[i];
                    float2 w2 = cmul(w1,w1), w3 = cmul(w1,w2), w4 = cmul(w2,w2);
                    float2 w5 = cmul(w2,w3), w6 = cmul(w3,w3), w7 = cmul(w3,w4);
                    u[i][1]=cmul(u[i][1],w1); u[i][2]=cmul(u[i][2],w2); u[i][3]=cmul(u[i][3],w3);
                    u[i][4]=cmul(u[i][4],w4); u[i][5]=cmul(u[i][5],w5); u[i][6]=cmul(u[i][6],w6);
                    u[i][7]=cmul(u[i][7],w7);
                }
            }
            #pragma unroll
            for (int q = 0; q < 8; ++q) {
                if (half_out && q >= 4) continue;       // never read downstream
                ch[PADA(baseA[i] + q*s)] = u[i][q];
            }
        }
        chan_sync(bar_id);
    }
}

// Copy padded twiddle image from gmem into smem (float4 vectors).
__device__ __forceinline__ void copy_twiddles(float2* tw, int tid){
    const float4* src = (const float4*)g_twp;
    float4* dst = (float4*)tw;
    #pragma unroll
    for (int i = 0; i < 3; ++i) {
        int idx = tid + NTHREADS * i;
        if (idx < TWPAD / 2) dst[idx] = src[idx];
    }
}

// ---------------------------------------------------------------------------
// Kernel 0: build padded twiddle table in gmem (once per launch; tiny).
// ---------------------------------------------------------------------------
__global__ void twinit_kernel()
{
    int j = blockIdx.x * blockDim.x + threadIdx.x;     // 0..2047
    if (j < 2048) {
        const float w = -2.0f * 3.14159265358979323846f / 4096.0f;
        float sv, cv;
        sincosf(w * (float)j, &sv, &cv);
        g_twp[PADA(j)] = make_float2(cv, sv);
    }
}

// ---------------------------------------------------------------------------
// Kernel A: T[k] = rfft(t, 8192) per d-channel, stored as (T[k], T[4096-k])
// float4 pairs at permuted index m (plus slot 2048 for the self-paired bin).
// ---------------------------------------------------------------------------
__global__ void __launch_bounds__(NTHREADS, 1)
tfft_kernel(const float* __restrict__ t)
{
    extern __shared__ float2 sm[];
    float2* tw = sm;
    const int tid  = threadIdx.x;
    const int ch   = tid >> 7;
    const int lane = tid & 127;
    const int bar  = ch + 1;
    float2* chd = sm + DATOFF + ch * CPAD;

    copy_twiddles(tw, tid);
    const float2 W0 = make_float2(W0_RE, W0_IM);

    const int dtile = blockIdx.x;                       // 0..255
    const float4* t4 = (const float4*)t + dtile;

    // stage in: z[j] = t[2j] + i t[2j+1], j = 0..4095
    #pragma unroll
    for (int i = 0; i < 8; ++i) {
        int j = tid + NTHREADS * i;
        float4 ve = t4[(size_t)(2*j)   * 256];
        float4 vo = t4[(size_t)(2*j+1) * 256];
        int a = PADA(j);
        sm[DATOFF + 0*CPAD + a] = make_float2(ve.x, vo.x);
        sm[DATOFF + 1*CPAD + a] = make_float2(ve.y, vo.y);
        sm[DATOFF + 2*CPAD + a] = make_float2(ve.z, vo.z);
        sm[DATOFF + 3*CPAD + a] = make_float2(ve.w, vo.w);
    }
    __syncthreads();                                    // cross-channel staging

    fft_stages<false, false, false>(chd, tw, lane, bar);

    float4* Tch = g_T + (size_t)(dtile*4 + ch) * TSTRIDE;
    for (int i = 0; i < 16; ++i) {
        int m = lane + (i << 7);
        if (m == 0) {
            float2 Z0 = chd[PADA(0)];
            Tch[0] = make_float4(Z0.x + Z0.y, 0.f, Z0.x - Z0.y, 0.f);   // (T[0], T[4096])
        } else {
            int k  = kOfM(m);
            float2 Zk = chd[PADA(rev12(k))];
            float2 Zm = chd[PADA(rev12(4096 - k))];
            float2 A = make_float2(0.5f*(Zk.x + Zm.x), 0.5f*(Zk.y - Zm.y));
            float2 B = make_float2(0.5f*(Zk.x - Zm.x), 0.5f*(Zk.y + Zm.y));
            float2 w = tw[PADA(k >> 1)];
            if (k & 1) w = cmul(w, W0);                 // e^{-i pi k / 4096}
            float2 WB = cmul(w, B);
            float2 Xk = make_float2(A.x + WB.y,  A.y - WB.x);
            float2 Xm = make_float2(A.x - WB.y, -(A.y + WB.x));
            Tch[m] = make_float4(Xk.x, Xk.y, Xm.x, Xm.y);
        }
    }
    if (lane == 0) {                                    // k = 2048 (self-paired), pos rev=4
        float2 Z = chd[PADA(4)];
        Tch[2048] = make_float4(Z.x, -Z.y, 0.f, 0.f);
    }
}

// ---------------------------------------------------------------------------
// Kernel B: per (b, d-tile): rfft(x pad 8192) -> * T -> irfft -> first 4096.
// ---------------------------------------------------------------------------
__global__ void __launch_bounds__(NTHREADS, 1)
conv_kernel(const float* __restrict__ x, float* __restrict__ out)
{
    extern __shared__ float2 sm[];
    float2* tw = sm;
    const int tid  = threadIdx.x;
    const int ch   = tid >> 7;
    const int lane = tid & 127;
    const int bar  = ch + 1;
    float2* chd = sm + DATOFF + ch * CPAD;

    copy_twiddles(tw, tid);
    const float2 W0 = make_float2(W0_RE, W0_IM);

    const int blk   = blockIdx.x;                       // 0..1023
    const int b     = blk >> 8;
    const int dtile = blk & 255;
    const float4* x4 = (const float4*)x + (size_t)b * 4096 * 256 + dtile;

    // stage in: z[j] = x[2j] + i x[2j+1] for j<2048.
    // Upper half [2048,4096) is implicit-zero: never stored, never loaded
    // (forward stage 0 uses dft8h and writes all 4096 slots before stage 1).
    #pragma unroll
    for (int i = 0; i < 4; ++i) {
        int j = tid + NTHREADS * i;                     // 0..2047
        float4 ve = x4[(size_t)(2*j)   * 256];
        float4 vo = x4[(size_t)(2*j+1) * 256];
        int a = PADA(j);
        sm[DATOFF + 0*CPAD + a] = make_float2(ve.x, vo.x);
        sm[DATOFF + 1*CPAD + a] = make_float2(ve.y, vo.y);
        sm[DATOFF + 2*CPAD + a] = make_float2(ve.z, vo.z);
        sm[DATOFF + 3*CPAD + a] = make_float2(ve.w, vo.w);
    }
    __syncthreads();                                    // cross-channel staging

    fft_stages<false, true, false>(chd, tw, lane, bar);

    // unpack -> multiply by T -> repack, all in scrambled order; fold 1/4096.
    const float4* Tch = g_T + (size_t)(dtile*4 + ch) * TSTRIDE;
    const float invM = 1.0f / 4096.0f;
    for (int i = 0; i < 16; ++i) {
        int m = lane + (i << 7);
        float4 Tp = Tch[m];
        if (m == 0) {
            float2 Z0 = chd[PADA(0)];
            float X0 = Z0.x + Z0.y;                     // X[0]
            float XM = Z0.x - Z0.y;                     // X[4096]
            float Y0 = X0 * Tp.x;
            float YM = XM * Tp.z;
            chd[PADA(0)] = make_float2(0.5f*(Y0+YM)*invM, 0.5f*(Y0-YM)*invM);
        } else {
            int k  = kOfM(m);
            int p1 = PADA(rev12(k));
            int p2 = PADA(rev12(4096 - k));
            float2 Zk = chd[p1];
            float2 Zm = chd[p2];
            float2 A = make_float2(0.5f*(Zk.x + Zm.x), 0.5f*(Zk.y - Zm.y));
            float2 B = make_float2(0.5f*(Zk.x - Zm.x), 0.5f*(Zk.y + Zm.y));
            float2 w = tw[PADA(k >> 1)];
            if (k & 1) w = cmul(w, W0);                 // e^{-i pi k / 4096}
            float2 WB = cmul(w, B);
            float2 Xk = make_float2(A.x + WB.y,  A.y - WB.x);
            float2 Xm = make_float2(A.x - WB.y, -(A.y + WB.x));
            float2 Yk = cmul(Xk, make_float2(Tp.x, Tp.y));
            float2 Ym = cmul(Xm, make_float2(Tp.z, Tp.w));
            float2 Cc = make_float2(0.5f*(Yk.x + Ym.x), 0.5f*(Yk.y - Ym.y));
            float2 Dd = make_float2(0.5f*(Yk.x - Ym.x), 0.5f*(Yk.y + Ym.y));
            float2 VD = cmulj(Dd, w);                   // conj(w) * D
            chd[p1] = make_float2((Cc.x - VD.y)*invM, ( Cc.y + VD.x)*invM);
            chd[p2] = make_float2((Cc.x + VD.y)*invM, (-Cc.y + VD.x)*invM);
        }
    }
    if (lane == 0) {                                    // k = 2048, pos rev=4
        float4 Tp = Tch[2048];
        float2 Z  = chd[PADA(4)];
        float2 X  = make_float2(Z.x, -Z.y);             // X[2048] = conj(Z[2048])
        float2 Y  = cmul(X, make_float2(Tp.x, Tp.y));
        chd[PADA(4)] = make_float2(Y.x * invM, -Y.y * invM);
    }
    chan_sync(bar);                                     // per-channel: pointwise done

    fft_stages<true, false, true>(chd, tw, lane, bar);

    __syncthreads();                                    // cross-channel before stage-out

    // stage out: y[2j] = Re z[j], y[2j+1] = Im z[j], j = 0..2047 (first 4096 samples)
    float4* o4 = (float4*)out + (size_t)b * 4096 * 256 + dtile;
    #pragma unroll
    for (int i = 0; i < 4; ++i) {
        int j = tid + NTHREADS * i;                     // 0..2047
        int a = PADA(j);
        float2 z0 = sm[DATOFF + 0*CPAD + a];
        float2 z1 = sm[DATOFF + 1*CPAD + a];
        float2 z2 = sm[DATOFF + 2*CPAD + a];
        float2 z3 = sm[DATOFF + 3*CPAD + a];
        o4[(size_t)(2*j)   * 256] = make_float4(z0.x, z1.x, z2.x, z3.x);
        o4[(size_t)(2*j+1) * 256] = make_float4(z0.y, z1.y, z2.y, z3.y);
    }
}

extern "C" void kernel_launch(void* const* d_in, const int* in_sizes, int n_in,
                              void* d_out, int out_size)
{
    const float* x = (const float*)d_in[0];   // (4, 4096, 1024) f32
    const float* t = (const float*)d_in[1];   // (8192, 1024) f32
    float* out = (float*)d_out;               // (4, 4096, 1024) f32

    cudaFuncSetAttribute(tfft_kernel, cudaFuncAttributeMaxDynamicSharedMemorySize, SMEM_BYTES);
    cudaFuncSetAttribute(conv_kernel, cudaFuncAttributeMaxDynamicSharedMemorySize, SMEM_BYTES);

    twinit_kernel<<<4, NTHREADS>>>();
    tfft_kernel<<<256, NTHREADS, SMEM_BYTES>>>(t);
    conv_kernel<<<1024, NTHREADS, SMEM_BYTES>>>(x, out);
}